// round 4
// baseline (speedup 1.0000x reference)
#include <cuda_runtime.h>

// GNNEncoder fused kernel, fp32 CUDA-core version.
// Math restructure: h2[n,f] = relu( b2[f] + sum_g Wa[f,g] v[n,g]
//                                  + sum_j A[n,j] * (sum_g Wb[f,g] v[j,g]) )
// where v[j,g] = relu(x_j*w1[g]+b1[g]),  A = row-normalized adj.
// Mapping: one warp per s-row, lane = f(=g) in [0,32). v and per-warp
// accumulators live in SMEM; A_norm in SMEM (uniform float4 broadcasts);
// qv[64] in registers.

namespace {
constexpr int kB  = 16;
constexpr int kS  = 2048;
constexpr int kN  = 64;
constexpr int kHD = 32;
constexpr int kWarps    = 4;     // warps per CTA
constexpr int kChunks   = 18;    // CTAs per batch element -> 288 CTAs total (~1 wave @2 CTA/SM)
constexpr int kWarpsPerB = kWarps * kChunks;  // 72
// smem: A[64*64] + rowinv[64] + per-warp v[64*32] + per-warp acc[64*32]
constexpr int kSmemFloats = kN * kN + kN + 2 * kWarps * kN * kHD;  // 20544
constexpr int kSmemBytes  = kSmemFloats * (int)sizeof(float);      // 82176
}

__global__ void gnn_zero_kernel(float* out, int n) {
    int i = blockIdx.x * blockDim.x + threadIdx.x;
    if (i < n) out[i] = 0.0f;
}

__global__ __launch_bounds__(128, 2)
void gnn_main_kernel(const float* __restrict__ x,
                     const float* __restrict__ adj,
                     const float* __restrict__ fc1_w,
                     const float* __restrict__ fc1_b,
                     const float* __restrict__ fc2_w,
                     const float* __restrict__ fc2_b,
                     float* __restrict__ out) {
    extern __shared__ float sm[];
    float* sA      = sm;                          // [64][64] normalized adjacency
    float* sRowInv = sm + kN * kN;                // [64]
    float* sVall   = sRowInv + kN;                // [4][64*32]
    float* sAccAll = sVall + kWarps * kN * kHD;   // [4][64*32]

    const int tid  = threadIdx.x;
    const int lane = tid & 31;
    const int w    = tid >> 5;
    const int b    = blockIdx.y;

    // --- one-time per-CTA setup: normalized adjacency + zero accumulators ---
    for (int i = tid; i < kN * kN; i += 128) sA[i] = adj[i];
    __syncthreads();
    if (tid < kN) {
        float ssum = 0.0f;
        #pragma unroll
        for (int j = 0; j < kN; j++) ssum += sA[tid * kN + j];
        sRowInv[tid] = 1.0f / (ssum + 1e-8f);
    }
    __syncthreads();
    for (int i = tid; i < kN * kN; i += 128) sA[i] *= sRowInv[i >> 6];
    for (int i = tid; i < kWarps * kN * kHD; i += 128) sAccAll[i] = 0.0f;

    // per-lane (f) weights in registers
    const float w1f = fc1_w[lane];
    const float b1f = fc1_b[lane];
    const float b2f = fc2_b[lane];
    float Wa[kHD], Wb[kHD];
    #pragma unroll
    for (int g4 = 0; g4 < kHD / 4; g4++) {
        float4 a4 = *reinterpret_cast<const float4*>(fc2_w + lane * 2 * kHD + 4 * g4);
        float4 b4 = *reinterpret_cast<const float4*>(fc2_w + lane * 2 * kHD + kHD + 4 * g4);
        Wa[4 * g4 + 0] = a4.x; Wa[4 * g4 + 1] = a4.y;
        Wa[4 * g4 + 2] = a4.z; Wa[4 * g4 + 3] = a4.w;
        Wb[4 * g4 + 0] = b4.x; Wb[4 * g4 + 1] = b4.y;
        Wb[4 * g4 + 2] = b4.z; Wb[4 * g4 + 3] = b4.w;
    }
    __syncthreads();

    float* vS   = sVall   + w * kN * kHD;
    float* accS = sAccAll + w * kN * kHD;

    const int wi = blockIdx.x * kWarps + w;  // warp index within batch element, [0,72)
    for (int s = wi; s < kS; s += kWarpsPerB) {
        const float* xr = x + ((size_t)b * kS + s) * kN;
        float x0 = xr[lane];
        float x1 = xr[32 + lane];

        __syncwarp();  // previous iteration's stage-3 reads of vS are done
        // --- stage 1: v[j][lane] = relu(x_j * w1 + b1), to SMEM ---
        #pragma unroll
        for (int j = 0; j < 32; j++) {
            float xj = __shfl_sync(0xffffffffu, x0, j);
            vS[j * kHD + lane] = fmaxf(fmaf(xj, w1f, b1f), 0.0f);
        }
        #pragma unroll
        for (int j = 0; j < 32; j++) {
            float xj = __shfl_sync(0xffffffffu, x1, j);
            vS[(32 + j) * kHD + lane] = fmaxf(fmaf(xj, w1f, b1f), 0.0f);
        }
        __syncwarp();

        // --- stage 2: qv[j] = sum_g Wb[lane,g] * v[j,g]   (uniform LDS.128) ---
        float qv[kN];
        #pragma unroll
        for (int j = 0; j < kN; j++) {
            const float4* vp = reinterpret_cast<const float4*>(vS + j * kHD);
            float q0 = 0.f, q1 = 0.f, q2 = 0.f, q3 = 0.f;
            #pragma unroll
            for (int g4 = 0; g4 < 8; g4++) {
                float4 v4 = vp[g4];
                q0 = fmaf(v4.x, Wb[4 * g4 + 0], q0);
                q1 = fmaf(v4.y, Wb[4 * g4 + 1], q1);
                q2 = fmaf(v4.z, Wb[4 * g4 + 2], q2);
                q3 = fmaf(v4.w, Wb[4 * g4 + 3], q3);
            }
            qv[j] = (q0 + q1) + (q2 + q3);
        }

        // --- stage 3: h2[n,lane] = relu(b2 + Wa.v[n] + sum_j A[n,j] qv[j]); acc += h2 ---
        #pragma unroll 2
        for (int n = 0; n < kN; n++) {
            const float4* vp = reinterpret_cast<const float4*>(vS + n * kHD);
            float p0 = b2f, p1 = 0.f, p2 = 0.f, p3 = 0.f;
            #pragma unroll
            for (int g4 = 0; g4 < 8; g4++) {
                float4 v4 = vp[g4];
                p0 = fmaf(v4.x, Wa[4 * g4 + 0], p0);
                p1 = fmaf(v4.y, Wa[4 * g4 + 1], p1);
                p2 = fmaf(v4.z, Wa[4 * g4 + 2], p2);
                p3 = fmaf(v4.w, Wa[4 * g4 + 3], p3);
            }
            const float4* ap = reinterpret_cast<const float4*>(sA + n * kN);
            #pragma unroll
            for (int j4 = 0; j4 < 16; j4++) {
                float4 a4 = ap[j4];
                p0 = fmaf(a4.x, qv[4 * j4 + 0], p0);
                p1 = fmaf(a4.y, qv[4 * j4 + 1], p1);
                p2 = fmaf(a4.z, qv[4 * j4 + 2], p2);
                p3 = fmaf(a4.w, qv[4 * j4 + 3], p3);
            }
            accS[n * kHD + lane] += fmaxf((p0 + p1) + (p2 + p3), 0.0f);
        }
    }
    __syncthreads();

    // --- CTA reduction over 4 warps + scaled atomicAdd to global ---
    const float inv = 1.0f / (float)kS;
    for (int i = tid; i < kN * kHD; i += 128) {
        float v = sAccAll[i]
                + sAccAll[kN * kHD + i]
                + sAccAll[2 * kN * kHD + i]
                + sAccAll[3 * kN * kHD + i];
        atomicAdd(out + (size_t)b * kN * kHD + i, v * inv);
    }
}

extern "C" void kernel_launch(void* const* d_in, const int* in_sizes, int n_in,
                              void* d_out, int out_size) {
    const float* x     = (const float*)d_in[0];
    const float* adj   = (const float*)d_in[1];
    const float* fc1_w = (const float*)d_in[2];
    const float* fc1_b = (const float*)d_in[3];
    const float* fc2_w = (const float*)d_in[4];
    const float* fc2_b = (const float*)d_in[5];
    float* out = (float*)d_out;

    cudaFuncSetAttribute(gnn_main_kernel,
                         cudaFuncAttributeMaxDynamicSharedMemorySize, kSmemBytes);

    gnn_zero_kernel<<<(kB * kN * kHD + 255) / 256, 256>>>(out, kB * kN * kHD);
    gnn_main_kernel<<<dim3(kChunks, kB), 128, kSmemBytes>>>(
        x, adj, fc1_w, fc1_b, fc2_w, fc2_b, out);
}

// round 7
// speedup vs baseline: 1.0004x; 1.0004x over previous
#include <cuda_runtime.h>

// GNNEncoder fused kernel, fp32 CUDA-core version.
// Math restructure: h2[n,f] = relu( b2[f] + sum_g Wa[f,g] v[n,g]
//                                  + sum_j A[n,j] * (sum_g Wb[f,g] v[j,g]) )
// where v[j,g] = relu(x_j*w1[g]+b1[g]),  A = row-normalized adj.
// Mapping: one warp per s-row, lane = f(=g) in [0,32). v and per-warp
// accumulators live in SMEM; A_norm in SMEM (uniform float4 broadcasts);
// qv[64] in registers.

namespace {
constexpr int kB  = 16;
constexpr int kS  = 2048;
constexpr int kN  = 64;
constexpr int kHD = 32;
constexpr int kWarps    = 4;     // warps per CTA
constexpr int kChunks   = 18;    // CTAs per batch element -> 288 CTAs total (~1 wave @2 CTA/SM)
constexpr int kWarpsPerB = kWarps * kChunks;  // 72
// smem: A[64*64] + rowinv[64] + per-warp v[64*32] + per-warp acc[64*32]
constexpr int kSmemFloats = kN * kN + kN + 2 * kWarps * kN * kHD;  // 20544
constexpr int kSmemBytes  = kSmemFloats * (int)sizeof(float);      // 82176
}

__global__ void gnn_zero_kernel(float* out, int n) {
    int i = blockIdx.x * blockDim.x + threadIdx.x;
    if (i < n) out[i] = 0.0f;
}

__global__ __launch_bounds__(128, 2)
void gnn_main_kernel(const float* __restrict__ x,
                     const float* __restrict__ adj,
                     const float* __restrict__ fc1_w,
                     const float* __restrict__ fc1_b,
                     const float* __restrict__ fc2_w,
                     const float* __restrict__ fc2_b,
                     float* __restrict__ out) {
    extern __shared__ float sm[];
    float* sA      = sm;                          // [64][64] normalized adjacency
    float* sRowInv = sm + kN * kN;                // [64]
    float* sVall   = sRowInv + kN;                // [4][64*32]
    float* sAccAll = sVall + kWarps * kN * kHD;   // [4][64*32]

    const int tid  = threadIdx.x;
    const int lane = tid & 31;
    const int w    = tid >> 5;
    const int b    = blockIdx.y;

    // --- one-time per-CTA setup: normalized adjacency + zero accumulators ---
    for (int i = tid; i < kN * kN; i += 128) sA[i] = adj[i];
    __syncthreads();
    if (tid < kN) {
        float ssum = 0.0f;
        #pragma unroll
        for (int j = 0; j < kN; j++) ssum += sA[tid * kN + j];
        sRowInv[tid] = 1.0f / (ssum + 1e-8f);
    }
    __syncthreads();
    for (int i = tid; i < kN * kN; i += 128) sA[i] *= sRowInv[i >> 6];
    for (int i = tid; i < kWarps * kN * kHD; i += 128) sAccAll[i] = 0.0f;

    // per-lane (f) weights in registers
    const float w1f = fc1_w[lane];
    const float b1f = fc1_b[lane];
    const float b2f = fc2_b[lane];
    float Wa[kHD], Wb[kHD];
    #pragma unroll
    for (int g4 = 0; g4 < kHD / 4; g4++) {
        float4 a4 = *reinterpret_cast<const float4*>(fc2_w + lane * 2 * kHD + 4 * g4);
        float4 b4 = *reinterpret_cast<const float4*>(fc2_w + lane * 2 * kHD + kHD + 4 * g4);
        Wa[4 * g4 + 0] = a4.x; Wa[4 * g4 + 1] = a4.y;
        Wa[4 * g4 + 2] = a4.z; Wa[4 * g4 + 3] = a4.w;
        Wb[4 * g4 + 0] = b4.x; Wb[4 * g4 + 1] = b4.y;
        Wb[4 * g4 + 2] = b4.z; Wb[4 * g4 + 3] = b4.w;
    }
    __syncthreads();

    float* vS   = sVall   + w * kN * kHD;
    float* accS = sAccAll + w * kN * kHD;

    const int wi = blockIdx.x * kWarps + w;  // warp index within batch element, [0,72)
    for (int s = wi; s < kS; s += kWarpsPerB) {
        const float* xr = x + ((size_t)b * kS + s) * kN;
        float x0 = xr[lane];
        float x1 = xr[32 + lane];

        __syncwarp();  // previous iteration's stage-3 reads of vS are done
        // --- stage 1: v[j][lane] = relu(x_j * w1 + b1), to SMEM ---
        #pragma unroll
        for (int j = 0; j < 32; j++) {
            float xj = __shfl_sync(0xffffffffu, x0, j);
            vS[j * kHD + lane] = fmaxf(fmaf(xj, w1f, b1f), 0.0f);
        }
        #pragma unroll
        for (int j = 0; j < 32; j++) {
            float xj = __shfl_sync(0xffffffffu, x1, j);
            vS[(32 + j) * kHD + lane] = fmaxf(fmaf(xj, w1f, b1f), 0.0f);
        }
        __syncwarp();

        // --- stage 2: qv[j] = sum_g Wb[lane,g] * v[j,g]   (uniform LDS.128) ---
        float qv[kN];
        #pragma unroll
        for (int j = 0; j < kN; j++) {
            const float4* vp = reinterpret_cast<const float4*>(vS + j * kHD);
            float q0 = 0.f, q1 = 0.f, q2 = 0.f, q3 = 0.f;
            #pragma unroll
            for (int g4 = 0; g4 < 8; g4++) {
                float4 v4 = vp[g4];
                q0 = fmaf(v4.x, Wb[4 * g4 + 0], q0);
                q1 = fmaf(v4.y, Wb[4 * g4 + 1], q1);
                q2 = fmaf(v4.z, Wb[4 * g4 + 2], q2);
                q3 = fmaf(v4.w, Wb[4 * g4 + 3], q3);
            }
            qv[j] = (q0 + q1) + (q2 + q3);
        }

        // --- stage 3: h2[n,lane] = relu(b2 + Wa.v[n] + sum_j A[n,j] qv[j]); acc += h2 ---
        #pragma unroll 2
        for (int n = 0; n < kN; n++) {
            const float4* vp = reinterpret_cast<const float4*>(vS + n * kHD);
            float p0 = b2f, p1 = 0.f, p2 = 0.f, p3 = 0.f;
            #pragma unroll
            for (int g4 = 0; g4 < 8; g4++) {
                float4 v4 = vp[g4];
                p0 = fmaf(v4.x, Wa[4 * g4 + 0], p0);
                p1 = fmaf(v4.y, Wa[4 * g4 + 1], p1);
                p2 = fmaf(v4.z, Wa[4 * g4 + 2], p2);
                p3 = fmaf(v4.w, Wa[4 * g4 + 3], p3);
            }
            const float4* ap = reinterpret_cast<const float4*>(sA + n * kN);
            #pragma unroll
            for (int j4 = 0; j4 < 16; j4++) {
                float4 a4 = ap[j4];
                p0 = fmaf(a4.x, qv[4 * j4 + 0], p0);
                p1 = fmaf(a4.y, qv[4 * j4 + 1], p1);
                p2 = fmaf(a4.z, qv[4 * j4 + 2], p2);
                p3 = fmaf(a4.w, qv[4 * j4 + 3], p3);
            }
            accS[n * kHD + lane] += fmaxf((p0 + p1) + (p2 + p3), 0.0f);
        }
    }
    __syncthreads();

    // --- CTA reduction over 4 warps + scaled atomicAdd to global ---
    const float inv = 1.0f / (float)kS;
    for (int i = tid; i < kN * kHD; i += 128) {
        float v = sAccAll[i]
                + sAccAll[kN * kHD + i]
                + sAccAll[2 * kN * kHD + i]
                + sAccAll[3 * kN * kHD + i];
        atomicAdd(out + (size_t)b * kN * kHD + i, v * inv);
    }
}

extern "C" void kernel_launch(void* const* d_in, const int* in_sizes, int n_in,
                              void* d_out, int out_size) {
    const float* x     = (const float*)d_in[0];
    const float* adj   = (const float*)d_in[1];
    const float* fc1_w = (const float*)d_in[2];
    const float* fc1_b = (const float*)d_in[3];
    const float* fc2_w = (const float*)d_in[4];
    const float* fc2_b = (const float*)d_in[5];
    float* out = (float*)d_out;

    cudaFuncSetAttribute(gnn_main_kernel,
                         cudaFuncAttributeMaxDynamicSharedMemorySize, kSmemBytes);

    gnn_zero_kernel<<<(kB * kN * kHD + 255) / 256, 256>>>(out, kB * kN * kHD);
    gnn_main_kernel<<<dim3(kChunks, kB), 128, kSmemBytes>>>(
        x, adj, fc1_w, fc1_b, fc2_w, fc2_b, out);
}

// round 10
// speedup vs baseline: 1.1311x; 1.1306x over previous
#include <cuda_runtime.h>

// GNNEncoder fused kernel, fp32 + packed f32x2 (FFMA2) version.
// h2[n,f] = relu( b2[f] + sum_g Wa[f,g] v[n,g]
//               + sum_j A[n,j] * (sum_g Wb[f,g] v[j,g]) )
// v[j,g] = relu(x_j*w1[g]+b1[g]),  A = row-normalized adj.
// Packing: along reduction dims (g-pairs, j-pairs) so both FFMA2 operands are
// naturally adjacent (LDS.128 -> two packed pairs; weights pre-packed in regs;
// qv pairs packed once per s-row).

namespace {
constexpr int kB  = 16;
constexpr int kS  = 2048;
constexpr int kN  = 64;
constexpr int kHD = 32;
constexpr int kWarps    = 4;     // warps per CTA
constexpr int kChunks   = 18;    // CTAs per batch element -> 288 CTAs total
constexpr int kWarpsPerB = kWarps * kChunks;  // 72
constexpr int kSmemFloats = kN * kN + kN + 2 * kWarps * kN * kHD;  // 20544
constexpr int kSmemBytes  = kSmemFloats * (int)sizeof(float);      // 82176
}

using u64 = unsigned long long;

__device__ __forceinline__ u64 pack2(float lo, float hi) {
    u64 r;
    asm("mov.b64 %0, {%1, %2};" : "=l"(r) : "f"(lo), "f"(hi));
    return r;
}
__device__ __forceinline__ void unpack2(u64 v, float& lo, float& hi) {
    asm("mov.b64 {%0, %1}, %2;" : "=f"(lo), "=f"(hi) : "l"(v));
}
__device__ __forceinline__ void fma2(u64& d, u64 a, u64 b) {
    asm("fma.rn.f32x2 %0, %1, %2, %0;" : "+l"(d) : "l"(a), "l"(b));
}
__device__ __forceinline__ u64 add2(u64 a, u64 b) {
    u64 r;
    asm("add.rn.f32x2 %0, %1, %2;" : "=l"(r) : "l"(a), "l"(b));
    return r;
}

__global__ void gnn_zero_kernel(float* out, int n) {
    int i = blockIdx.x * blockDim.x + threadIdx.x;
    if (i < n) out[i] = 0.0f;
}

__global__ __launch_bounds__(128, 2)
void gnn_main_kernel(const float* __restrict__ x,
                     const float* __restrict__ adj,
                     const float* __restrict__ fc1_w,
                     const float* __restrict__ fc1_b,
                     const float* __restrict__ fc2_w,
                     const float* __restrict__ fc2_b,
                     float* __restrict__ out) {
    extern __shared__ float sm[];
    float* sA      = sm;                          // [64][64] normalized adjacency
    float* sRowInv = sm + kN * kN;                // [64]
    float* sVall   = sRowInv + kN;                // [4][64*32]
    float* sAccAll = sVall + kWarps * kN * kHD;   // [4][64*32]

    const int tid  = threadIdx.x;
    const int lane = tid & 31;
    const int w    = tid >> 5;
    const int b    = blockIdx.y;

    // --- one-time per-CTA setup: normalized adjacency + zero accumulators ---
    for (int i = tid; i < kN * kN; i += 128) sA[i] = adj[i];
    __syncthreads();
    if (tid < kN) {
        float ssum = 0.0f;
        #pragma unroll
        for (int j = 0; j < kN; j++) ssum += sA[tid * kN + j];
        sRowInv[tid] = 1.0f / (ssum + 1e-8f);
    }
    __syncthreads();
    for (int i = tid; i < kN * kN; i += 128) sA[i] *= sRowInv[i >> 6];
    for (int i = tid; i < kWarps * kN * kHD; i += 128) sAccAll[i] = 0.0f;

    // per-lane (f) scalars
    const float w1f = fc1_w[lane];
    const float b1f = fc1_b[lane];
    const float b2f = fc2_b[lane];

    // packed weights: natural (g, g+1) pairs. Row of fc2_w is 64 floats = 256B,
    // 16B-aligned -> load as ulonglong2 (each .x/.y is one packed f32 pair).
    u64 Wa_pk[kHD / 2], Wb_pk[kHD / 2];
    {
        const ulonglong2* wrow =
            reinterpret_cast<const ulonglong2*>(fc2_w + lane * 2 * kHD);
        #pragma unroll
        for (int i = 0; i < 8; i++) {       // Wa = cols [0,32)
            ulonglong2 t = wrow[i];
            Wa_pk[2 * i + 0] = t.x;
            Wa_pk[2 * i + 1] = t.y;
        }
        #pragma unroll
        for (int i = 0; i < 8; i++) {       // Wb = cols [32,64)
            ulonglong2 t = wrow[8 + i];
            Wb_pk[2 * i + 0] = t.x;
            Wb_pk[2 * i + 1] = t.y;
        }
    }
    __syncthreads();

    float* vS   = sVall   + w * kN * kHD;
    float* accS = sAccAll + w * kN * kHD;

    const int wi = blockIdx.x * kWarps + w;  // warp index within batch element
    for (int s = wi; s < kS; s += kWarpsPerB) {
        const float* xr = x + ((size_t)b * kS + s) * kN;
        float x0 = xr[lane];
        float x1 = xr[32 + lane];

        __syncwarp();  // previous iteration's stage-3 reads of vS are done
        // --- stage 1: v[j][lane] = relu(x_j * w1 + b1), to SMEM ---
        #pragma unroll
        for (int j = 0; j < 32; j++) {
            float xj = __shfl_sync(0xffffffffu, x0, j);
            vS[j * kHD + lane] = fmaxf(fmaf(xj, w1f, b1f), 0.0f);
        }
        #pragma unroll
        for (int j = 0; j < 32; j++) {
            float xj = __shfl_sync(0xffffffffu, x1, j);
            vS[(32 + j) * kHD + lane] = fmaxf(fmaf(xj, w1f, b1f), 0.0f);
        }
        __syncwarp();

        // --- stage 2: qv[j] = sum_g Wb[lane,g] * v[j,g]  (packed over g),
        //     emitted directly as packed (j, j+1) pairs for stage 3 ---
        u64 qpk[kN / 2];
        #pragma unroll
        for (int j2 = 0; j2 < kN / 2; j2++) {
            float q[2];
            #pragma unroll
            for (int h = 0; h < 2; h++) {
                const ulonglong2* vp = reinterpret_cast<const ulonglong2*>(
                    vS + (2 * j2 + h) * kHD);
                u64 a0 = 0ull, a1 = 0ull;
                #pragma unroll
                for (int i = 0; i < 8; i++) {
                    ulonglong2 t = vp[i];
                    fma2(a0, t.x, Wb_pk[2 * i + 0]);
                    fma2(a1, t.y, Wb_pk[2 * i + 1]);
                }
                float lo, hi;
                unpack2(add2(a0, a1), lo, hi);
                q[h] = lo + hi;
            }
            qpk[j2] = pack2(q[0], q[1]);
        }

        // --- stage 3: h2[n,lane] = relu(b2 + Wa.v[n] + sum_j A[n,j] qv[j]) ---
        #pragma unroll 2
        for (int n = 0; n < kN; n++) {
            const ulonglong2* vp =
                reinterpret_cast<const ulonglong2*>(vS + n * kHD);
            u64 p0 = 0ull, p1 = 0ull;
            #pragma unroll
            for (int i = 0; i < 8; i++) {
                ulonglong2 t = vp[i];
                fma2(p0, t.x, Wa_pk[2 * i + 0]);
                fma2(p1, t.y, Wa_pk[2 * i + 1]);
            }
            const ulonglong2* ap =
                reinterpret_cast<const ulonglong2*>(sA + n * kN);
            u64 r0 = 0ull, r1 = 0ull;
            #pragma unroll
            for (int i = 0; i < 16; i++) {
                ulonglong2 t = ap[i];
                fma2(r0, t.x, qpk[2 * i + 0]);
                fma2(r1, t.y, qpk[2 * i + 1]);
            }
            float lo, hi;
            unpack2(add2(add2(p0, p1), add2(r0, r1)), lo, hi);
            accS[n * kHD + lane] += fmaxf(lo + hi + b2f, 0.0f);
        }
    }
    __syncthreads();

    // --- CTA reduction over 4 warps + scaled atomicAdd to global ---
    const float inv = 1.0f / (float)kS;
    for (int i = tid; i < kN * kHD; i += 128) {
        float v = sAccAll[i]
                + sAccAll[kN * kHD + i]
                + sAccAll[2 * kN * kHD + i]
                + sAccAll[3 * kN * kHD + i];
        atomicAdd(out + (size_t)b * kN * kHD + i, v * inv);
    }
}

extern "C" void kernel_launch(void* const* d_in, const int* in_sizes, int n_in,
                              void* d_out, int out_size) {
    const float* x     = (const float*)d_in[0];
    const float* adj   = (const float*)d_in[1];
    const float* fc1_w = (const float*)d_in[2];
    const float* fc1_b = (const float*)d_in[3];
    const float* fc2_w = (const float*)d_in[4];
    const float* fc2_b = (const float*)d_in[5];
    float* out = (float*)d_out;

    cudaFuncSetAttribute(gnn_main_kernel,
                         cudaFuncAttributeMaxDynamicSharedMemorySize, kSmemBytes);

    gnn_zero_kernel<<<(kB * kN * kHD + 255) / 256, 256>>>(out, kB * kN * kHD);
    gnn_main_kernel<<<dim3(kChunks, kB), 128, kSmemBytes>>>(
        x, adj, fc1_w, fc1_b, fc2_w, fc2_b, out);
}

// round 11
// speedup vs baseline: 1.1322x; 1.0010x over previous
#include <cuda_runtime.h>

// GNNEncoder fused kernel, fp32 + packed f32x2 (FFMA2) version.
// h2[n,f] = relu( b2[f] + sum_g Wa[f,g] v[n,g]
//               + sum_j A[n,j] * (sum_g Wb[f,g] v[j,g]) )
// v[j,g] = relu(x_j*w1[g]+b1[g]),  A = row-normalized adj.
// Packing: along reduction dims (g-pairs, j-pairs) so both FFMA2 operands are
// naturally adjacent (LDS.128 -> two packed pairs; weights pre-packed in regs;
// qv pairs packed once per s-row).

namespace {
constexpr int kB  = 16;
constexpr int kS  = 2048;
constexpr int kN  = 64;
constexpr int kHD = 32;
constexpr int kWarps    = 4;     // warps per CTA
constexpr int kChunks   = 18;    // CTAs per batch element -> 288 CTAs total
constexpr int kWarpsPerB = kWarps * kChunks;  // 72
constexpr int kSmemFloats = kN * kN + kN + 2 * kWarps * kN * kHD;  // 20544
constexpr int kSmemBytes  = kSmemFloats * (int)sizeof(float);      // 82176
}

using u64 = unsigned long long;

__device__ __forceinline__ u64 pack2(float lo, float hi) {
    u64 r;
    asm("mov.b64 %0, {%1, %2};" : "=l"(r) : "f"(lo), "f"(hi));
    return r;
}
__device__ __forceinline__ void unpack2(u64 v, float& lo, float& hi) {
    asm("mov.b64 {%0, %1}, %2;" : "=f"(lo), "=f"(hi) : "l"(v));
}
__device__ __forceinline__ void fma2(u64& d, u64 a, u64 b) {
    asm("fma.rn.f32x2 %0, %1, %2, %0;" : "+l"(d) : "l"(a), "l"(b));
}
__device__ __forceinline__ u64 add2(u64 a, u64 b) {
    u64 r;
    asm("add.rn.f32x2 %0, %1, %2;" : "=l"(r) : "l"(a), "l"(b));
    return r;
}

__global__ void gnn_zero_kernel(float* out, int n) {
    int i = blockIdx.x * blockDim.x + threadIdx.x;
    if (i < n) out[i] = 0.0f;
}

__global__ __launch_bounds__(128, 2)
void gnn_main_kernel(const float* __restrict__ x,
                     const float* __restrict__ adj,
                     const float* __restrict__ fc1_w,
                     const float* __restrict__ fc1_b,
                     const float* __restrict__ fc2_w,
                     const float* __restrict__ fc2_b,
                     float* __restrict__ out) {
    extern __shared__ float sm[];
    float* sA      = sm;                          // [64][64] normalized adjacency
    float* sRowInv = sm + kN * kN;                // [64]
    float* sVall   = sRowInv + kN;                // [4][64*32]
    float* sAccAll = sVall + kWarps * kN * kHD;   // [4][64*32]

    const int tid  = threadIdx.x;
    const int lane = tid & 31;
    const int w    = tid >> 5;
    const int b    = blockIdx.y;

    // --- one-time per-CTA setup: normalized adjacency + zero accumulators ---
    for (int i = tid; i < kN * kN; i += 128) sA[i] = adj[i];
    __syncthreads();
    if (tid < kN) {
        float ssum = 0.0f;
        #pragma unroll
        for (int j = 0; j < kN; j++) ssum += sA[tid * kN + j];
        sRowInv[tid] = 1.0f / (ssum + 1e-8f);
    }
    __syncthreads();
    for (int i = tid; i < kN * kN; i += 128) sA[i] *= sRowInv[i >> 6];
    for (int i = tid; i < kWarps * kN * kHD; i += 128) sAccAll[i] = 0.0f;

    // per-lane (f) scalars
    const float w1f = fc1_w[lane];
    const float b1f = fc1_b[lane];
    const float b2f = fc2_b[lane];

    // packed weights: natural (g, g+1) pairs. Row of fc2_w is 64 floats = 256B,
    // 16B-aligned -> load as ulonglong2 (each .x/.y is one packed f32 pair).
    u64 Wa_pk[kHD / 2], Wb_pk[kHD / 2];
    {
        const ulonglong2* wrow =
            reinterpret_cast<const ulonglong2*>(fc2_w + lane * 2 * kHD);
        #pragma unroll
        for (int i = 0; i < 8; i++) {       // Wa = cols [0,32)
            ulonglong2 t = wrow[i];
            Wa_pk[2 * i + 0] = t.x;
            Wa_pk[2 * i + 1] = t.y;
        }
        #pragma unroll
        for (int i = 0; i < 8; i++) {       // Wb = cols [32,64)
            ulonglong2 t = wrow[8 + i];
            Wb_pk[2 * i + 0] = t.x;
            Wb_pk[2 * i + 1] = t.y;
        }
    }
    __syncthreads();

    float* vS   = sVall   + w * kN * kHD;
    float* accS = sAccAll + w * kN * kHD;

    const int wi = blockIdx.x * kWarps + w;  // warp index within batch element
    for (int s = wi; s < kS; s += kWarpsPerB) {
        const float* xr = x + ((size_t)b * kS + s) * kN;
        float x0 = xr[lane];
        float x1 = xr[32 + lane];

        __syncwarp();  // previous iteration's stage-3 reads of vS are done
        // --- stage 1: v[j][lane] = relu(x_j * w1 + b1), to SMEM ---
        #pragma unroll
        for (int j = 0; j < 32; j++) {
            float xj = __shfl_sync(0xffffffffu, x0, j);
            vS[j * kHD + lane] = fmaxf(fmaf(xj, w1f, b1f), 0.0f);
        }
        #pragma unroll
        for (int j = 0; j < 32; j++) {
            float xj = __shfl_sync(0xffffffffu, x1, j);
            vS[(32 + j) * kHD + lane] = fmaxf(fmaf(xj, w1f, b1f), 0.0f);
        }
        __syncwarp();

        // --- stage 2: qv[j] = sum_g Wb[lane,g] * v[j,g]  (packed over g),
        //     emitted directly as packed (j, j+1) pairs for stage 3 ---
        u64 qpk[kN / 2];
        #pragma unroll
        for (int j2 = 0; j2 < kN / 2; j2++) {
            float q[2];
            #pragma unroll
            for (int h = 0; h < 2; h++) {
                const ulonglong2* vp = reinterpret_cast<const ulonglong2*>(
                    vS + (2 * j2 + h) * kHD);
                u64 a0 = 0ull, a1 = 0ull;
                #pragma unroll
                for (int i = 0; i < 8; i++) {
                    ulonglong2 t = vp[i];
                    fma2(a0, t.x, Wb_pk[2 * i + 0]);
                    fma2(a1, t.y, Wb_pk[2 * i + 1]);
                }
                float lo, hi;
                unpack2(add2(a0, a1), lo, hi);
                q[h] = lo + hi;
            }
            qpk[j2] = pack2(q[0], q[1]);
        }

        // --- stage 3: h2[n,lane] = relu(b2 + Wa.v[n] + sum_j A[n,j] qv[j]) ---
        #pragma unroll 2
        for (int n = 0; n < kN; n++) {
            const ulonglong2* vp =
                reinterpret_cast<const ulonglong2*>(vS + n * kHD);
            u64 p0 = 0ull, p1 = 0ull;
            #pragma unroll
            for (int i = 0; i < 8; i++) {
                ulonglong2 t = vp[i];
                fma2(p0, t.x, Wa_pk[2 * i + 0]);
                fma2(p1, t.y, Wa_pk[2 * i + 1]);
            }
            const ulonglong2* ap =
                reinterpret_cast<const ulonglong2*>(sA + n * kN);
            u64 r0 = 0ull, r1 = 0ull;
            #pragma unroll
            for (int i = 0; i < 16; i++) {
                ulonglong2 t = ap[i];
                fma2(r0, t.x, qpk[2 * i + 0]);
                fma2(r1, t.y, qpk[2 * i + 1]);
            }
            float lo, hi;
            unpack2(add2(add2(p0, p1), add2(r0, r1)), lo, hi);
            accS[n * kHD + lane] += fmaxf(lo + hi + b2f, 0.0f);
        }
    }
    __syncthreads();

    // --- CTA reduction over 4 warps + scaled atomicAdd to global ---
    const float inv = 1.0f / (float)kS;
    for (int i = tid; i < kN * kHD; i += 128) {
        float v = sAccAll[i]
                + sAccAll[kN * kHD + i]
                + sAccAll[2 * kN * kHD + i]
                + sAccAll[3 * kN * kHD + i];
        atomicAdd(out + (size_t)b * kN * kHD + i, v * inv);
    }
}

extern "C" void kernel_launch(void* const* d_in, const int* in_sizes, int n_in,
                              void* d_out, int out_size) {
    const float* x     = (const float*)d_in[0];
    const float* adj   = (const float*)d_in[1];
    const float* fc1_w = (const float*)d_in[2];
    const float* fc1_b = (const float*)d_in[3];
    const float* fc2_w = (const float*)d_in[4];
    const float* fc2_b = (const float*)d_in[5];
    float* out = (float*)d_out;

    cudaFuncSetAttribute(gnn_main_kernel,
                         cudaFuncAttributeMaxDynamicSharedMemorySize, kSmemBytes);

    gnn_zero_kernel<<<(kB * kN * kHD + 255) / 256, 256>>>(out, kB * kN * kHD);
    gnn_main_kernel<<<dim3(kChunks, kB), 128, kSmemBytes>>>(
        x, adj, fc1_w, fc1_b, fc2_w, fc2_b, out);
}

// round 12
// speedup vs baseline: 1.2116x; 1.0701x over previous
#include <cuda_runtime.h>

// GNNEncoder fused kernel, fp32 + packed f32x2 (FFMA2), pv-fusion version.
// h2[n,f] = relu( b2[f] + pv[n,f] + sum_j A[n,j] * qv[j,f] )
//   pv[n,f] = sum_g Wa[f,g] v[n,g]   (fused into the single v-row pass)
//   qv[j,f] = sum_g Wb[f,g] v[j,g]
//   v[j,g]  = relu(x_j*w1[g]+b1[g]),  A = row-normalized adj.
// v rows are read from SMEM exactly ONCE per s-row (stage 2 computes both
// dots from the same loaded registers); pv goes through a small per-warp
// SMEM buffer read back as lane-distinct LDS.32 in stage 3.

namespace {
constexpr int kB  = 16;
constexpr int kS  = 2048;
constexpr int kN  = 64;
constexpr int kHD = 32;
constexpr int kWarps    = 4;     // warps per CTA
constexpr int kChunks   = 18;    // CTAs per batch element -> 288 CTAs total
constexpr int kWarpsPerB = kWarps * kChunks;  // 72
// smem: A[64*64] + rowinv[64] + per-warp {v, pv, acc}[64*32]
constexpr int kSmemFloats = kN * kN + kN + 3 * kWarps * kN * kHD;  // 28736
constexpr int kSmemBytes  = kSmemFloats * (int)sizeof(float);      // 114944
}

using u64 = unsigned long long;

__device__ __forceinline__ u64 pack2(float lo, float hi) {
    u64 r;
    asm("mov.b64 %0, {%1, %2};" : "=l"(r) : "f"(lo), "f"(hi));
    return r;
}
__device__ __forceinline__ void unpack2(u64 v, float& lo, float& hi) {
    asm("mov.b64 {%0, %1}, %2;" : "=f"(lo), "=f"(hi) : "l"(v));
}
__device__ __forceinline__ void fma2(u64& d, u64 a, u64 b) {
    asm("fma.rn.f32x2 %0, %1, %2, %0;" : "+l"(d) : "l"(a), "l"(b));
}
__device__ __forceinline__ u64 add2(u64 a, u64 b) {
    u64 r;
    asm("add.rn.f32x2 %0, %1, %2;" : "=l"(r) : "l"(a), "l"(b));
    return r;
}

__global__ void gnn_zero_kernel(float* out, int n) {
    int i = blockIdx.x * blockDim.x + threadIdx.x;
    if (i < n) out[i] = 0.0f;
}

__global__ __launch_bounds__(128, 2)
void gnn_main_kernel(const float* __restrict__ x,
                     const float* __restrict__ adj,
                     const float* __restrict__ fc1_w,
                     const float* __restrict__ fc1_b,
                     const float* __restrict__ fc2_w,
                     const float* __restrict__ fc2_b,
                     float* __restrict__ out) {
    extern __shared__ float sm[];
    float* sA      = sm;                          // [64][64] normalized adjacency
    float* sRowInv = sm + kN * kN;                // [64]
    float* sVall   = sRowInv + kN;                // [4][64*32] v rows
    float* sPvAll  = sVall  + kWarps * kN * kHD;  // [4][64*32] pv (Wa.v + b2)
    float* sAccAll = sPvAll + kWarps * kN * kHD;  // [4][64*32] accumulators

    const int tid  = threadIdx.x;
    const int lane = tid & 31;
    const int w    = tid >> 5;
    const int b    = blockIdx.y;

    // --- one-time per-CTA setup: normalized adjacency + zero accumulators ---
    for (int i = tid; i < kN * kN; i += 128) sA[i] = adj[i];
    __syncthreads();
    if (tid < kN) {
        float ssum = 0.0f;
        #pragma unroll
        for (int j = 0; j < kN; j++) ssum += sA[tid * kN + j];
        sRowInv[tid] = 1.0f / (ssum + 1e-8f);
    }
    __syncthreads();
    for (int i = tid; i < kN * kN; i += 128) sA[i] *= sRowInv[i >> 6];
    for (int i = tid; i < kWarps * kN * kHD; i += 128) sAccAll[i] = 0.0f;

    // per-lane (f) scalars
    const float w1f = fc1_w[lane];
    const float b1f = fc1_b[lane];
    const float b2f = fc2_b[lane];

    // packed weights: natural (g, g+1) pairs from row f of fc2_w (64 floats).
    u64 Wa_pk[kHD / 2], Wb_pk[kHD / 2];
    {
        const ulonglong2* wrow =
            reinterpret_cast<const ulonglong2*>(fc2_w + lane * 2 * kHD);
        #pragma unroll
        for (int i = 0; i < 8; i++) {       // Wa = cols [0,32)
            ulonglong2 t = wrow[i];
            Wa_pk[2 * i + 0] = t.x;
            Wa_pk[2 * i + 1] = t.y;
        }
        #pragma unroll
        for (int i = 0; i < 8; i++) {       // Wb = cols [32,64)
            ulonglong2 t = wrow[8 + i];
            Wb_pk[2 * i + 0] = t.x;
            Wb_pk[2 * i + 1] = t.y;
        }
    }
    __syncthreads();

    float* vS   = sVall   + w * kN * kHD;
    float* pvS  = sPvAll  + w * kN * kHD;
    float* accS = sAccAll + w * kN * kHD;

    const int wi = blockIdx.x * kWarps + w;  // warp index within batch element
    for (int s = wi; s < kS; s += kWarpsPerB) {
        const float* xr = x + ((size_t)b * kS + s) * kN;
        float x0 = xr[lane];
        float x1 = xr[32 + lane];

        __syncwarp();  // previous iteration's stage-2 reads of vS are done
        // --- stage 1: v[j][lane] = relu(x_j * w1 + b1), to SMEM ---
        #pragma unroll
        for (int j = 0; j < 32; j++) {
            float xj = __shfl_sync(0xffffffffu, x0, j);
            vS[j * kHD + lane] = fmaxf(fmaf(xj, w1f, b1f), 0.0f);
        }
        #pragma unroll
        for (int j = 0; j < 32; j++) {
            float xj = __shfl_sync(0xffffffffu, x1, j);
            vS[(32 + j) * kHD + lane] = fmaxf(fmaf(xj, w1f, b1f), 0.0f);
        }
        __syncwarp();

        // --- stage 2 (fused): single pass over v rows computes BOTH
        //     qv[r] = Wb.v[r] (packed (r,r+1) pairs in regs) and
        //     pv[r] = Wa.v[r] + b2 (to SMEM, read back lane-distinct) ---
        u64 qpk[kN / 2];
        #pragma unroll
        for (int r2 = 0; r2 < kN / 2; r2++) {
            const ulonglong2* vp0 =
                reinterpret_cast<const ulonglong2*>(vS + (2 * r2 + 0) * kHD);
            const ulonglong2* vp1 =
                reinterpret_cast<const ulonglong2*>(vS + (2 * r2 + 1) * kHD);
            u64 qa0 = 0ull, qa1 = 0ull, pa0 = 0ull, pa1 = 0ull;
            u64 qb0 = 0ull, qb1 = 0ull, pb0 = 0ull, pb1 = 0ull;
            #pragma unroll
            for (int i = 0; i < 8; i++) {
                ulonglong2 t0 = vp0[i];
                ulonglong2 t1 = vp1[i];
                fma2(qa0, t0.x, Wb_pk[2 * i + 0]);
                fma2(qa1, t0.y, Wb_pk[2 * i + 1]);
                fma2(pa0, t0.x, Wa_pk[2 * i + 0]);
                fma2(pa1, t0.y, Wa_pk[2 * i + 1]);
                fma2(qb0, t1.x, Wb_pk[2 * i + 0]);
                fma2(qb1, t1.y, Wb_pk[2 * i + 1]);
                fma2(pb0, t1.x, Wa_pk[2 * i + 0]);
                fma2(pb1, t1.y, Wa_pk[2 * i + 1]);
            }
            float lo, hi;
            float q0, q1, p0, p1;
            unpack2(add2(qa0, qa1), lo, hi); q0 = lo + hi;
            unpack2(add2(qb0, qb1), lo, hi); q1 = lo + hi;
            qpk[r2] = pack2(q0, q1);
            unpack2(add2(pa0, pa1), lo, hi); p0 = lo + hi;
            unpack2(add2(pb0, pb1), lo, hi); p1 = lo + hi;
            pvS[(2 * r2 + 0) * kHD + lane] = p0 + b2f;  // same-lane readback: no sync needed
            pvS[(2 * r2 + 1) * kHD + lane] = p1 + b2f;
        }

        // --- stage 3: h2[n,lane] = relu(pv[n] + sum_j A[n,j] qv[j]) ---
        #pragma unroll 2
        for (int n = 0; n < kN; n++) {
            const ulonglong2* ap =
                reinterpret_cast<const ulonglong2*>(sA + n * kN);
            u64 r0 = 0ull, r1 = 0ull;
            #pragma unroll
            for (int i = 0; i < 16; i++) {
                ulonglong2 t = ap[i];
                fma2(r0, t.x, qpk[2 * i + 0]);
                fma2(r1, t.y, qpk[2 * i + 1]);
            }
            float lo, hi;
            unpack2(add2(r0, r1), lo, hi);
            float h2 = fmaxf(lo + hi + pvS[n * kHD + lane], 0.0f);
            accS[n * kHD + lane] += h2;
        }
    }
    __syncthreads();

    // --- CTA reduction over 4 warps + scaled atomicAdd to global ---
    const float inv = 1.0f / (float)kS;
    for (int i = tid; i < kN * kHD; i += 128) {
        float v = sAccAll[i]
                + sAccAll[kN * kHD + i]
                + sAccAll[2 * kN * kHD + i]
                + sAccAll[3 * kN * kHD + i];
        atomicAdd(out + (size_t)b * kN * kHD + i, v * inv);
    }
}

extern "C" void kernel_launch(void* const* d_in, const int* in_sizes, int n_in,
                              void* d_out, int out_size) {
    const float* x     = (const float*)d_in[0];
    const float* adj   = (const float*)d_in[1];
    const float* fc1_w = (const float*)d_in[2];
    const float* fc1_b = (const float*)d_in[3];
    const float* fc2_w = (const float*)d_in[4];
    const float* fc2_b = (const float*)d_in[5];
    float* out = (float*)d_out;

    cudaFuncSetAttribute(gnn_main_kernel,
                         cudaFuncAttributeMaxDynamicSharedMemorySize, kSmemBytes);

    gnn_zero_kernel<<<(kB * kN * kHD + 255) / 256, 256>>>(out, kB * kN * kHD);
    gnn_main_kernel<<<dim3(kChunks, kB), 128, kSmemBytes>>>(
        x, adj, fc1_w, fc1_b, fc2_w, fc2_b, out);
}

// round 13
// speedup vs baseline: 1.2862x; 1.0615x over previous
#include <cuda_runtime.h>

// GNNEncoder fused kernel: fp32 + FFMA2 + pv-fusion + s-PAIRING.
// Per warp iteration, TWO s-rows are processed so that stage 3 loads each
// normalized-adjacency row ONCE for both rows (4 independent FFMA2 chains),
// and the accumulator RMW is done once per n for both rows.
// pv of row s1 is stowed in the vS buffer (free after stage 2), so SMEM is
// unchanged and 2 CTAs/SM are preserved.

namespace {
constexpr int kB  = 16;
constexpr int kS  = 2048;
constexpr int kN  = 64;
constexpr int kHD = 32;
constexpr int kWarps    = 4;     // warps per CTA
constexpr int kChunks   = 18;    // CTAs per batch element -> 288 CTAs total
constexpr int kWarpsPerB = kWarps * kChunks;  // 72
// smem: A[64*64] + rowinv[64] + per-warp {v, pv, acc}[64*32]
constexpr int kSmemFloats = kN * kN + kN + 3 * kWarps * kN * kHD;  // 28736
constexpr int kSmemBytes  = kSmemFloats * (int)sizeof(float);      // 114944
}

using u64 = unsigned long long;

__device__ __forceinline__ u64 pack2(float lo, float hi) {
    u64 r;
    asm("mov.b64 %0, {%1, %2};" : "=l"(r) : "f"(lo), "f"(hi));
    return r;
}
__device__ __forceinline__ void unpack2(u64 v, float& lo, float& hi) {
    asm("mov.b64 {%0, %1}, %2;" : "=f"(lo), "=f"(hi) : "l"(v));
}
__device__ __forceinline__ void fma2(u64& d, u64 a, u64 b) {
    asm("fma.rn.f32x2 %0, %1, %2, %0;" : "+l"(d) : "l"(a), "l"(b));
}
__device__ __forceinline__ u64 add2(u64 a, u64 b) {
    u64 r;
    asm("add.rn.f32x2 %0, %1, %2;" : "=l"(r) : "l"(a), "l"(b));
    return r;
}

// Both dot products (Wb.v -> q, Wa.v -> p) from ONE pass over a v row.
__device__ __forceinline__ void dot_row(const float* __restrict__ vrow,
                                        const u64* __restrict__ Wa,
                                        const u64* __restrict__ Wb,
                                        float& q, float& p) {
    const ulonglong2* vp = reinterpret_cast<const ulonglong2*>(vrow);
    u64 qa0 = 0ull, qa1 = 0ull, pa0 = 0ull, pa1 = 0ull;
    #pragma unroll
    for (int i = 0; i < 8; i++) {
        ulonglong2 t = vp[i];
        fma2(qa0, t.x, Wb[2 * i + 0]);
        fma2(qa1, t.y, Wb[2 * i + 1]);
        fma2(pa0, t.x, Wa[2 * i + 0]);
        fma2(pa1, t.y, Wa[2 * i + 1]);
    }
    float lo, hi;
    unpack2(add2(qa0, qa1), lo, hi); q = lo + hi;
    unpack2(add2(pa0, pa1), lo, hi); p = lo + hi;
}

__global__ void gnn_zero_kernel(float* out, int n) {
    int i = blockIdx.x * blockDim.x + threadIdx.x;
    if (i < n) out[i] = 0.0f;
}

__global__ __launch_bounds__(128, 2)
void gnn_main_kernel(const float* __restrict__ x,
                     const float* __restrict__ adj,
                     const float* __restrict__ fc1_w,
                     const float* __restrict__ fc1_b,
                     const float* __restrict__ fc2_w,
                     const float* __restrict__ fc2_b,
                     float* __restrict__ out) {
    extern __shared__ float sm[];
    float* sA      = sm;                          // [64][64] normalized adjacency
    float* sRowInv = sm + kN * kN;                // [64]
    float* sVall   = sRowInv + kN;                // [4][64*32] v rows / pv(s1)
    float* sPvAll  = sVall  + kWarps * kN * kHD;  // [4][64*32] pv(s0)
    float* sAccAll = sPvAll + kWarps * kN * kHD;  // [4][64*32] accumulators

    const int tid  = threadIdx.x;
    const int lane = tid & 31;
    const int w    = tid >> 5;
    const int b    = blockIdx.y;

    // --- one-time per-CTA setup: normalized adjacency + zero accumulators ---
    for (int i = tid; i < kN * kN; i += 128) sA[i] = adj[i];
    __syncthreads();
    if (tid < kN) {
        float ssum = 0.0f;
        #pragma unroll
        for (int j = 0; j < kN; j++) ssum += sA[tid * kN + j];
        sRowInv[tid] = 1.0f / (ssum + 1e-8f);
    }
    __syncthreads();
    for (int i = tid; i < kN * kN; i += 128) sA[i] *= sRowInv[i >> 6];
    for (int i = tid; i < kWarps * kN * kHD; i += 128) sAccAll[i] = 0.0f;

    // per-lane (f) scalars
    const float w1f = fc1_w[lane];
    const float b1f = fc1_b[lane];
    const float b2f = fc2_b[lane];

    // packed weights: natural (g, g+1) pairs from row f of fc2_w (64 floats).
    u64 Wa_pk[kHD / 2], Wb_pk[kHD / 2];
    {
        const ulonglong2* wrow =
            reinterpret_cast<const ulonglong2*>(fc2_w + lane * 2 * kHD);
        #pragma unroll
        for (int i = 0; i < 8; i++) {       // Wa = cols [0,32)
            ulonglong2 t = wrow[i];
            Wa_pk[2 * i + 0] = t.x;
            Wa_pk[2 * i + 1] = t.y;
        }
        #pragma unroll
        for (int i = 0; i < 8; i++) {       // Wb = cols [32,64)
            ulonglong2 t = wrow[8 + i];
            Wb_pk[2 * i + 0] = t.x;
            Wb_pk[2 * i + 1] = t.y;
        }
    }
    __syncthreads();

    float* vS   = sVall   + w * kN * kHD;
    float* pvS  = sPvAll  + w * kN * kHD;
    float* accS = sAccAll + w * kN * kHD;

    const int wi = blockIdx.x * kWarps + w;  // warp index within batch element
    // pair loop: warp handles (s0, s0+1); 2*wi in [0,144) strides cover all
    // even starts of [0,2048) exactly once.
    for (int s0 = 2 * wi; s0 < kS; s0 += 2 * kWarpsPerB) {
        u64 qpk0[kN / 2], qpk1[kN / 2];

        // ================= row s0: stage 1 + stage 2 =================
        {
            const float* xr = x + ((size_t)b * kS + s0) * kN;
            float x0 = xr[lane];
            float x1 = xr[32 + lane];
            __syncwarp();  // prior iteration's cross-lane vS reads done
            #pragma unroll
            for (int j = 0; j < 32; j++) {
                float xj = __shfl_sync(0xffffffffu, x0, j);
                vS[j * kHD + lane] = fmaxf(fmaf(xj, w1f, b1f), 0.0f);
            }
            #pragma unroll
            for (int j = 0; j < 32; j++) {
                float xj = __shfl_sync(0xffffffffu, x1, j);
                vS[(32 + j) * kHD + lane] = fmaxf(fmaf(xj, w1f, b1f), 0.0f);
            }
            __syncwarp();
            #pragma unroll
            for (int r2 = 0; r2 < kN / 2; r2++) {
                float q0, p0, q1, p1;
                dot_row(vS + (2 * r2 + 0) * kHD, Wa_pk, Wb_pk, q0, p0);
                dot_row(vS + (2 * r2 + 1) * kHD, Wa_pk, Wb_pk, q1, p1);
                qpk0[r2] = pack2(q0, q1);
                pvS[(2 * r2 + 0) * kHD + lane] = p0 + b2f;
                pvS[(2 * r2 + 1) * kHD + lane] = p1 + b2f;
            }
        }

        // ================= row s1: stage 1 + stage 2 =================
        {
            const float* xr = x + ((size_t)b * kS + s0 + 1) * kN;
            float x0 = xr[lane];
            float x1 = xr[32 + lane];
            __syncwarp();  // s0's cross-lane vS reads done before overwrite
            #pragma unroll
            for (int j = 0; j < 32; j++) {
                float xj = __shfl_sync(0xffffffffu, x0, j);
                vS[j * kHD + lane] = fmaxf(fmaf(xj, w1f, b1f), 0.0f);
            }
            #pragma unroll
            for (int j = 0; j < 32; j++) {
                float xj = __shfl_sync(0xffffffffu, x1, j);
                vS[(32 + j) * kHD + lane] = fmaxf(fmaf(xj, w1f, b1f), 0.0f);
            }
            __syncwarp();
            #pragma unroll
            for (int r2 = 0; r2 < kN / 2; r2++) {
                float q0, p0, q1, p1;
                // reads of rows 2r2, 2r2+1 complete (program order, this warp)
                dot_row(vS + (2 * r2 + 0) * kHD, Wa_pk, Wb_pk, q0, p0);
                dot_row(vS + (2 * r2 + 1) * kHD, Wa_pk, Wb_pk, q1, p1);
                qpk1[r2] = pack2(q0, q1);
                // stow pv(s1) into vS (rows already consumed; same-lane addr)
                vS[(2 * r2 + 0) * kHD + lane] = p0 + b2f;
                vS[(2 * r2 + 1) * kHD + lane] = p1 + b2f;
            }
        }

        // ===== stage 3: one A-row pass serves BOTH s-rows =====
        #pragma unroll 2
        for (int n = 0; n < kN; n++) {
            const ulonglong2* ap =
                reinterpret_cast<const ulonglong2*>(sA + n * kN);
            u64 r0 = 0ull, r1 = 0ull, r2 = 0ull, r3 = 0ull;
            #pragma unroll
            for (int i = 0; i < 16; i++) {
                ulonglong2 t = ap[i];
                fma2(r0, t.x, qpk0[2 * i + 0]);
                fma2(r1, t.y, qpk0[2 * i + 1]);
                fma2(r2, t.x, qpk1[2 * i + 0]);
                fma2(r3, t.y, qpk1[2 * i + 1]);
            }
            float lo, hi;
            unpack2(add2(r0, r1), lo, hi);
            float h0 = fmaxf(lo + hi + pvS[n * kHD + lane], 0.0f);
            unpack2(add2(r2, r3), lo, hi);
            float h1 = fmaxf(lo + hi + vS[n * kHD + lane], 0.0f);
            accS[n * kHD + lane] += h0 + h1;
        }
    }
    __syncthreads();

    // --- CTA reduction over 4 warps + scaled atomicAdd to global ---
    const float inv = 1.0f / (float)kS;
    for (int i = tid; i < kN * kHD; i += 128) {
        float v = sAccAll[i]
                + sAccAll[kN * kHD + i]
                + sAccAll[2 * kN * kHD + i]
                + sAccAll[3 * kN * kHD + i];
        atomicAdd(out + (size_t)b * kN * kHD + i, v * inv);
    }
}

extern "C" void kernel_launch(void* const* d_in, const int* in_sizes, int n_in,
                              void* d_out, int out_size) {
    const float* x     = (const float*)d_in[0];
    const float* adj   = (const float*)d_in[1];
    const float* fc1_w = (const float*)d_in[2];
    const float* fc1_b = (const float*)d_in[3];
    const float* fc2_w = (const float*)d_in[4];
    const float* fc2_b = (const float*)d_in[5];
    float* out = (float*)d_out;

    cudaFuncSetAttribute(gnn_main_kernel,
                         cudaFuncAttributeMaxDynamicSharedMemorySize, kSmemBytes);

    gnn_zero_kernel<<<(kB * kN * kHD + 255) / 256, 256>>>(out, kB * kN * kHD);
    gnn_main_kernel<<<dim3(kChunks, kB), 128, kSmemBytes>>>(
        x, adj, fc1_w, fc1_b, fc2_w, fc2_b, out);
}

// round 14
// speedup vs baseline: 1.8181x; 1.4136x over previous
#include <cuda_runtime.h>

// GNNEncoder fused kernel: interval-table restructure.
// v[j,g] = relu(x_j*w1_g + b1_g) is piecewise-linear in scalar x_j with 32
// breakpoints t_g = -b1_g/w1_g. Within each of 33 sorted-threshold intervals
// the relu active-set is constant, so
//   qv[j,f] = x_j*SwB[k_j,f] + SbB[k_j,f],   pv[j,f] = x_j*SwA[k_j,f] + SbA[k_j,f]
// with k_j = #(sorted thresholds < x_j). Tables (33 x 32 x float4) built once
// per CTA. Stage 3 keeps the s-paired A.qv pass (FFMA2, 4 chains) and computes
// pv on the fly. No v/pv buffers -> ~70KB SMEM, 3 CTAs/SM.

namespace {
constexpr int kB  = 16;
constexpr int kS  = 2048;
constexpr int kN  = 64;
constexpr int kHD = 32;
constexpr int kWarps    = 4;
constexpr int kChunks   = 27;                 // 432 CTAs total (~3/SM)
constexpr int kWarpsPerB = kWarps * kChunks;  // 108
constexpr int kNK = 33;                       // intervals

// SMEM float offsets
constexpr int OFF_A      = 0;                 // [64*64] normalized adjacency
constexpr int OFF_ROWINV = 4096;              // [64]
constexpr int OFF_T      = 4160;              // [32] sorted thresholds
constexpr int OFF_RANK   = 4192;              // [32] ranks (as int)
constexpr int OFF_TAB    = 4224;              // [33*32] float4 = 4224 floats
constexpr int OFF_XK     = 8448;              // [4 warps][2 rows][64] float2 = 1024
constexpr int OFF_ACC    = 9472;              // [4 warps][64*32] = 8192
constexpr int kSmemFloats = 17664;
constexpr int kSmemBytes  = kSmemFloats * (int)sizeof(float);  // 70656
}

using u64 = unsigned long long;

__device__ __forceinline__ u64 pack2(float lo, float hi) {
    u64 r;
    asm("mov.b64 %0, {%1, %2};" : "=l"(r) : "f"(lo), "f"(hi));
    return r;
}
__device__ __forceinline__ void unpack2(u64 v, float& lo, float& hi) {
    asm("mov.b64 {%0, %1}, %2;" : "=f"(lo), "=f"(hi) : "l"(v));
}
__device__ __forceinline__ void fma2(u64& d, u64 a, u64 b) {
    asm("fma.rn.f32x2 %0, %1, %2, %0;" : "+l"(d) : "l"(a), "l"(b));
}
__device__ __forceinline__ u64 add2(u64 a, u64 b) {
    u64 r;
    asm("add.rn.f32x2 %0, %1, %2;" : "=l"(r) : "l"(a), "l"(b));
    return r;
}

// k = #{sorted thresholds < x}, 6-step biased binary search over 32 elements.
__device__ __forceinline__ int bsearch32(const float* __restrict__ sT, float x) {
    int k = 0;
    #pragma unroll
    for (int step = 32; step >= 1; step >>= 1)
        if (k + step <= 32 && sT[k + step - 1] < x) k += step;
    return k;
}

__global__ void gnn_zero_kernel(float* out, int n) {
    int i = blockIdx.x * blockDim.x + threadIdx.x;
    if (i < n) out[i] = 0.0f;
}

__global__ __launch_bounds__(128, 3)
void gnn_main_kernel(const float* __restrict__ x,
                     const float* __restrict__ adj,
                     const float* __restrict__ fc1_w,
                     const float* __restrict__ fc1_b,
                     const float* __restrict__ fc2_w,
                     const float* __restrict__ fc2_b,
                     float* __restrict__ out) {
    extern __shared__ float sm[];
    float* sA    = sm + OFF_A;
    float* sRInv = sm + OFF_ROWINV;
    float* sT    = sm + OFF_T;
    int*   sRank = reinterpret_cast<int*>(sm + OFF_RANK);
    float* sTab  = sm + OFF_TAB;   // float4[33][32]: (SwA, SbA, SwB, SbB)
    float* sXK   = sm + OFF_XK;
    float* sAcc  = sm + OFF_ACC;

    const int tid  = threadIdx.x;
    const int lane = tid & 31;
    const int w    = tid >> 5;
    const int b    = blockIdx.y;

    // ---------- one-time setup ----------
    // normalized adjacency
    for (int i = tid; i < kN * kN; i += 128) sA[i] = adj[i];
    __syncthreads();
    if (tid < kN) {
        float ssum = 0.0f;
        #pragma unroll
        for (int j = 0; j < kN; j++) ssum += sA[tid * kN + j];
        sRInv[tid] = 1.0f / (ssum + 1e-8f);
    }
    __syncthreads();
    for (int i = tid; i < kN * kN; i += 128) sA[i] *= sRInv[i >> 6];

    // thresholds + ranks (warp 0)
    if (tid < 32) {
        float w1 = fc1_w[tid], b1 = fc1_b[tid];
        float t = -b1 / w1;
        int rank = 0;
        #pragma unroll
        for (int h = 0; h < 32; h++) {
            float th = __shfl_sync(0xffffffffu, t, h);
            rank += (th < t) || (th == t && h < tid);
        }
        sT[rank] = t;
        sRank[tid] = rank;
    }
    // zero per-warp accumulators
    for (int i = tid; i < kWarps * kN * kHD; i += 128) sAcc[i] = 0.0f;
    __syncthreads();

    // interval tables: for interval k, g active iff
    //   w1g>0: rank_g < k;  w1g<0: rank_g >= k;  w1g==0: b1g>0
    for (int idx = tid; idx < kNK * kHD; idx += 128) {
        int k = idx >> 5;
        int f = idx & 31;
        float swa = 0.f, sba = 0.f, swb = 0.f, sbb = 0.f;
        #pragma unroll 4
        for (int g = 0; g < 32; g++) {
            float w1 = fc1_w[g], b1 = fc1_b[g];
            int rank = sRank[g];
            bool active = (w1 > 0.f) ? (rank < k)
                          : ((w1 < 0.f) ? (rank >= k) : (b1 > 0.f));
            if (active) {
                float wa = fc2_w[f * 2 * kHD + g];
                float wb = fc2_w[f * 2 * kHD + kHD + g];
                swa = fmaf(wa, w1, swa); sba = fmaf(wa, b1, sba);
                swb = fmaf(wb, w1, swb); sbb = fmaf(wb, b1, sbb);
            }
        }
        reinterpret_cast<float4*>(sTab)[idx] = make_float4(swa, sba, swb, sbb);
    }
    __syncthreads();

    const float b2f = fc2_b[lane];
    float2* xk0 = reinterpret_cast<float2*>(sXK + w * 256);        // row0 [64]
    float2* xk1 = reinterpret_cast<float2*>(sXK + w * 256 + 128);  // row1 [64]
    float*  accS = sAcc + w * kN * kHD;
    const char* tabB = reinterpret_cast<const char*>(sTab);

    const int wi = blockIdx.x * kWarps + w;   // [0, 108)
    for (int s0 = 2 * wi; s0 < kS; s0 += 2 * kWarpsPerB) {
        __syncwarp();  // prior iteration's xk reads complete
        // ---- per-row: load x, find interval, publish (x, tab byte-offset) ----
        #pragma unroll
        for (int r = 0; r < 2; r++) {
            const float* xr = x + ((size_t)b * kS + (s0 + r)) * kN;
            float xlo = xr[lane];
            float xhi = xr[32 + lane];
            int klo = bsearch32(sT, xlo);
            int khi = bsearch32(sT, xhi);
            float2* xkr = r ? xk1 : xk0;
            xkr[lane]      = make_float2(xlo, __int_as_float(klo * 512));
            xkr[32 + lane] = make_float2(xhi, __int_as_float(khi * 512));
        }
        __syncwarp();

        // ---- stage 2: qv via table lookup, packed (j, j+1) pairs ----
        u64 qpk0[kN / 2], qpk1[kN / 2];
        #pragma unroll
        for (int j2 = 0; j2 < kN / 2; j2++) {
            float2 a0 = xk0[2 * j2], c0 = xk0[2 * j2 + 1];
            float4 ta = *(reinterpret_cast<const float4*>(
                              tabB + __float_as_int(a0.y)) + lane);
            float4 tc = *(reinterpret_cast<const float4*>(
                              tabB + __float_as_int(c0.y)) + lane);
            qpk0[j2] = pack2(fmaf(a0.x, ta.z, ta.w), fmaf(c0.x, tc.z, tc.w));
            float2 a1 = xk1[2 * j2], c1 = xk1[2 * j2 + 1];
            float4 tb = *(reinterpret_cast<const float4*>(
                              tabB + __float_as_int(a1.y)) + lane);
            float4 td = *(reinterpret_cast<const float4*>(
                              tabB + __float_as_int(c1.y)) + lane);
            qpk1[j2] = pack2(fmaf(a1.x, tb.z, tb.w), fmaf(c1.x, td.z, td.w));
        }

        // ---- stage 3: one A-row pass serves both rows; pv on the fly ----
        #pragma unroll 2
        for (int n = 0; n < kN; n++) {
            const ulonglong2* ap =
                reinterpret_cast<const ulonglong2*>(sA + n * kN);
            u64 r0 = 0ull, r1 = 0ull, r2 = 0ull, r3 = 0ull;
            #pragma unroll
            for (int i = 0; i < 16; i++) {
                ulonglong2 t = ap[i];
                fma2(r0, t.x, qpk0[2 * i + 0]);
                fma2(r1, t.y, qpk0[2 * i + 1]);
                fma2(r2, t.x, qpk1[2 * i + 0]);
                fma2(r3, t.y, qpk1[2 * i + 1]);
            }
            float2 c0 = xk0[n];  // uniform broadcasts
            float2 c1 = xk1[n];
            float4 t0 = *(reinterpret_cast<const float4*>(
                              tabB + __float_as_int(c0.y)) + lane);
            float4 t1 = *(reinterpret_cast<const float4*>(
                              tabB + __float_as_int(c1.y)) + lane);
            float pv0 = fmaf(c0.x, t0.x, t0.y) + b2f;
            float pv1 = fmaf(c1.x, t1.x, t1.y) + b2f;
            float lo, hi;
            unpack2(add2(r0, r1), lo, hi);
            float h0 = fmaxf(lo + hi + pv0, 0.0f);
            unpack2(add2(r2, r3), lo, hi);
            float h1 = fmaxf(lo + hi + pv1, 0.0f);
            accS[n * kHD + lane] += h0 + h1;
        }
    }
    __syncthreads();

    // ---- CTA reduction over 4 warps + scaled atomicAdd to global ----
    const float inv = 1.0f / (float)kS;
    for (int i = tid; i < kN * kHD; i += 128) {
        float v = sAcc[i]
                + sAcc[kN * kHD + i]
                + sAcc[2 * kN * kHD + i]
                + sAcc[3 * kN * kHD + i];
        atomicAdd(out + (size_t)b * kN * kHD + i, v * inv);
    }
}

extern "C" void kernel_launch(void* const* d_in, const int* in_sizes, int n_in,
                              void* d_out, int out_size) {
    const float* x     = (const float*)d_in[0];
    const float* adj   = (const float*)d_in[1];
    const float* fc1_w = (const float*)d_in[2];
    const float* fc1_b = (const float*)d_in[3];
    const float* fc2_w = (const float*)d_in[4];
    const float* fc2_b = (const float*)d_in[5];
    float* out = (float*)d_out;

    cudaFuncSetAttribute(gnn_main_kernel,
                         cudaFuncAttributeMaxDynamicSharedMemorySize, kSmemBytes);

    gnn_zero_kernel<<<(kB * kN * kHD + 255) / 256, 256>>>(out, kB * kN * kHD);
    gnn_main_kernel<<<dim3(kChunks, kB), 128, kSmemBytes>>>(
        x, adj, fc1_w, fc1_b, fc2_w, fc2_b, out);
}

// round 15
// speedup vs baseline: 1.8822x; 1.0353x over previous
#include <cuda_runtime.h>

// GNNEncoder fused kernel: interval-table restructure, SPLIT float2 tables.
//   qv[j,f] = x_j*SwB[k_j,f] + SbB[k_j,f]   (TabQ, stage 2)
//   pv[j,f] = x_j*SwA[k_j,f] + SbA[k_j,f]   (TabP, stage 3, on the fly)
// k_j = #(sorted relu thresholds < x_j); tables built once per CTA.
// Split tables halve table-lookup wavefronts (float2 instead of float4);
// per-row metadata packed as float4 xkP[n] = (x0, byteoff0, x1, byteoff1).
// Stage 3 keeps s-paired A.qv pass (FFMA2, 4 independent chains).

namespace {
constexpr int kB  = 16;
constexpr int kS  = 2048;
constexpr int kN  = 64;
constexpr int kHD = 32;
constexpr int kWarps    = 4;
constexpr int kChunks   = 27;                 // 432 CTAs (~3/SM, one wave)
constexpr int kWarpsPerB = kWarps * kChunks;  // 108
constexpr int kNK = 33;                       // intervals

// SMEM float offsets
constexpr int OFF_A      = 0;                 // [64*64] normalized adjacency
constexpr int OFF_ROWINV = 4096;              // [64]
constexpr int OFF_T      = 4160;              // [32] sorted thresholds
constexpr int OFF_RANK   = 4192;              // [32] ranks (int)
constexpr int OFF_TABQ   = 4224;              // float2[33][32] (SwB,SbB) = 2112 floats
constexpr int OFF_TABP   = 6336;              // float2[33][32] (SwA,SbA) = 2112 floats
constexpr int OFF_XK     = 8448;              // [4 warps][64] float4 = 1024 floats
constexpr int OFF_ACC    = 9472;              // [4 warps][64*32] = 8192 floats
constexpr int kSmemFloats = 17664;
constexpr int kSmemBytes  = kSmemFloats * (int)sizeof(float);  // 70656
}

using u64 = unsigned long long;

__device__ __forceinline__ u64 pack2(float lo, float hi) {
    u64 r;
    asm("mov.b64 %0, {%1, %2};" : "=l"(r) : "f"(lo), "f"(hi));
    return r;
}
__device__ __forceinline__ void unpack2(u64 v, float& lo, float& hi) {
    asm("mov.b64 {%0, %1}, %2;" : "=f"(lo), "=f"(hi) : "l"(v));
}
__device__ __forceinline__ void fma2(u64& d, u64 a, u64 b) {
    asm("fma.rn.f32x2 %0, %1, %2, %0;" : "+l"(d) : "l"(a), "l"(b));
}
__device__ __forceinline__ u64 add2(u64 a, u64 b) {
    u64 r;
    asm("add.rn.f32x2 %0, %1, %2;" : "=l"(r) : "l"(a), "l"(b));
    return r;
}

// k = #{sorted thresholds < x}, 6-step binary search over 32 elements.
__device__ __forceinline__ int bsearch32(const float* __restrict__ sT, float x) {
    int k = 0;
    #pragma unroll
    for (int step = 32; step >= 1; step >>= 1)
        if (k + step <= 32 && sT[k + step - 1] < x) k += step;
    return k;
}

__global__ void gnn_zero_kernel(float* out, int n) {
    int i = blockIdx.x * blockDim.x + threadIdx.x;
    if (i < n) out[i] = 0.0f;
}

__global__ __launch_bounds__(128, 3)
void gnn_main_kernel(const float* __restrict__ x,
                     const float* __restrict__ adj,
                     const float* __restrict__ fc1_w,
                     const float* __restrict__ fc1_b,
                     const float* __restrict__ fc2_w,
                     const float* __restrict__ fc2_b,
                     float* __restrict__ out) {
    extern __shared__ float sm[];
    float* sA    = sm + OFF_A;
    float* sRInv = sm + OFF_ROWINV;
    float* sT    = sm + OFF_T;
    int*   sRank = reinterpret_cast<int*>(sm + OFF_RANK);
    float* sTabQ = sm + OFF_TABQ;
    float* sTabP = sm + OFF_TABP;
    float* sXK   = sm + OFF_XK;
    float* sAcc  = sm + OFF_ACC;

    const int tid  = threadIdx.x;
    const int lane = tid & 31;
    const int w    = tid >> 5;
    const int b    = blockIdx.y;

    // ---------- one-time setup ----------
    for (int i = tid; i < kN * kN; i += 128) sA[i] = adj[i];
    __syncthreads();
    if (tid < kN) {
        float ssum = 0.0f;
        #pragma unroll
        for (int j = 0; j < kN; j++) ssum += sA[tid * kN + j];
        sRInv[tid] = 1.0f / (ssum + 1e-8f);
    }
    __syncthreads();
    for (int i = tid; i < kN * kN; i += 128) sA[i] *= sRInv[i >> 6];

    // thresholds + ranks (warp 0)
    if (tid < 32) {
        float w1 = fc1_w[tid], b1 = fc1_b[tid];
        float t = -b1 / w1;
        int rank = 0;
        #pragma unroll
        for (int h = 0; h < 32; h++) {
            float th = __shfl_sync(0xffffffffu, t, h);
            rank += (th < t) || (th == t && h < tid);
        }
        sT[rank] = t;
        sRank[tid] = rank;
    }
    for (int i = tid; i < kWarps * kN * kHD; i += 128) sAcc[i] = 0.0f;
    __syncthreads();

    // split interval tables: g active iff
    //   w1g>0: rank_g < k;  w1g<0: rank_g >= k;  w1g==0: b1g>0
    for (int idx = tid; idx < kNK * kHD; idx += 128) {
        int k = idx >> 5;
        int f = idx & 31;
        float swa = 0.f, sba = 0.f, swb = 0.f, sbb = 0.f;
        #pragma unroll 4
        for (int g = 0; g < 32; g++) {
            float w1 = fc1_w[g], b1 = fc1_b[g];
            int rank = sRank[g];
            bool active = (w1 > 0.f) ? (rank < k)
                          : ((w1 < 0.f) ? (rank >= k) : (b1 > 0.f));
            if (active) {
                float wa = fc2_w[f * 2 * kHD + g];
                float wb = fc2_w[f * 2 * kHD + kHD + g];
                swa = fmaf(wa, w1, swa); sba = fmaf(wa, b1, sba);
                swb = fmaf(wb, w1, swb); sbb = fmaf(wb, b1, sbb);
            }
        }
        reinterpret_cast<float2*>(sTabQ)[idx] = make_float2(swb, sbb);
        reinterpret_cast<float2*>(sTabP)[idx] = make_float2(swa, sba);
    }
    __syncthreads();

    const float b2f = fc2_b[lane];
    float4* xkP = reinterpret_cast<float4*>(sXK + w * 256);  // [64]
    float*  accS = sAcc + w * kN * kHD;
    const char* tabQB = reinterpret_cast<const char*>(sTabQ);
    const char* tabPB = reinterpret_cast<const char*>(sTabP);

    const int wi = blockIdx.x * kWarps + w;   // [0, 108)
    for (int s0 = 2 * wi; s0 < kS; s0 += 2 * kWarpsPerB) {
        __syncwarp();  // prior iteration's xkP reads complete
        // ---- publish (x, table byte-offset) for both rows, packed float4 ----
        {
            const float* xr0 = x + ((size_t)b * kS + s0) * kN;
            const float* xr1 = xr0 + kN;
            float xa0 = xr0[lane], xa1 = xr0[32 + lane];
            float xb0 = xr1[lane], xb1 = xr1[32 + lane];
            int ka0 = bsearch32(sT, xa0) * 256;  // byte offset: k * 32 * 8B
            int ka1 = bsearch32(sT, xa1) * 256;
            int kb0 = bsearch32(sT, xb0) * 256;
            int kb1 = bsearch32(sT, xb1) * 256;
            xkP[lane]      = make_float4(xa0, __int_as_float(ka0),
                                         xb0, __int_as_float(kb0));
            xkP[32 + lane] = make_float4(xa1, __int_as_float(ka1),
                                         xb1, __int_as_float(kb1));
        }
        __syncwarp();

        // ---- stage 2: qv via TabQ lookups, packed (j, j+1) pairs ----
        u64 qpk0[kN / 2], qpk1[kN / 2];
        #pragma unroll
        for (int j2 = 0; j2 < kN / 2; j2++) {
            float4 u = xkP[2 * j2];
            float4 v = xkP[2 * j2 + 1];
            float2 ta = *(reinterpret_cast<const float2*>(
                              tabQB + __float_as_int(u.y)) + lane);
            float2 tc = *(reinterpret_cast<const float2*>(
                              tabQB + __float_as_int(v.y)) + lane);
            float2 tb = *(reinterpret_cast<const float2*>(
                              tabQB + __float_as_int(u.w)) + lane);
            float2 td = *(reinterpret_cast<const float2*>(
                              tabQB + __float_as_int(v.w)) + lane);
            qpk0[j2] = pack2(fmaf(u.x, ta.x, ta.y), fmaf(v.x, tc.x, tc.y));
            qpk1[j2] = pack2(fmaf(u.z, tb.x, tb.y), fmaf(v.z, td.x, td.y));
        }

        // ---- stage 3: one A-row pass serves both rows; pv via TabP ----
        #pragma unroll 2
        for (int n = 0; n < kN; n++) {
            const ulonglong2* ap =
                reinterpret_cast<const ulonglong2*>(sA + n * kN);
            u64 r0 = 0ull, r1 = 0ull, r2 = 0ull, r3 = 0ull;
            #pragma unroll
            for (int i = 0; i < 16; i++) {
                ulonglong2 t = ap[i];
                fma2(r0, t.x, qpk0[2 * i + 0]);
                fma2(r1, t.y, qpk0[2 * i + 1]);
                fma2(r2, t.x, qpk1[2 * i + 0]);
                fma2(r3, t.y, qpk1[2 * i + 1]);
            }
            float4 u = xkP[n];  // uniform broadcast, 1 LDS.128
            float2 tp0 = *(reinterpret_cast<const float2*>(
                               tabPB + __float_as_int(u.y)) + lane);
            float2 tp1 = *(reinterpret_cast<const float2*>(
                               tabPB + __float_as_int(u.w)) + lane);
            float pv0 = fmaf(u.x, tp0.x, tp0.y) + b2f;
            float pv1 = fmaf(u.z, tp1.x, tp1.y) + b2f;
            float lo, hi;
            unpack2(add2(r0, r1), lo, hi);
            float h0 = fmaxf(lo + hi + pv0, 0.0f);
            unpack2(add2(r2, r3), lo, hi);
            float h1 = fmaxf(lo + hi + pv1, 0.0f);
            accS[n * kHD + lane] += h0 + h1;
        }
    }
    __syncthreads();

    // ---- CTA reduction over 4 warps + scaled atomicAdd to global ----
    const float inv = 1.0f / (float)kS;
    for (int i = tid; i < kN * kHD; i += 128) {
        float v = sAcc[i]
                + sAcc[kN * kHD + i]
                + sAcc[2 * kN * kHD + i]
                + sAcc[3 * kN * kHD + i];
        atomicAdd(out + (size_t)b * kN * kHD + i, v * inv);
    }
}

extern "C" void kernel_launch(void* const* d_in, const int* in_sizes, int n_in,
                              void* d_out, int out_size) {
    const float* x     = (const float*)d_in[0];
    const float* adj   = (const float*)d_in[1];
    const float* fc1_w = (const float*)d_in[2];
    const float* fc1_b = (const float*)d_in[3];
    const float* fc2_w = (const float*)d_in[4];
    const float* fc2_b = (const float*)d_in[5];
    float* out = (float*)d_out;

    cudaFuncSetAttribute(gnn_main_kernel,
                         cudaFuncAttributeMaxDynamicSharedMemorySize, kSmemBytes);

    gnn_zero_kernel<<<(kB * kN * kHD + 255) / 256, 256>>>(out, kB * kN * kHD);
    gnn_main_kernel<<<dim3(kChunks, kB), 128, kSmemBytes>>>(
        x, adj, fc1_w, fc1_b, fc2_w, fc2_b, out);
}